// round 12
// baseline (speedup 1.0000x reference)
#include <cuda_runtime.h>
#include <cuda_bf16.h>
#include <cstdint>
#include <math.h>

#define T_MAX 2048
#define B_SZ  16
#define D_SZ  1024
#define M_ROWS (T_MAX * B_SZ)      // 32768
#define N_TILES 256                 // 128-row tiles; tile j = timesteps 8j..8j+7
#define SCAN_BLOCKS 128
#define GEMM_BLOCKS (N_TILES * 2)   // (bm, bn)

// proj row m = t*16+b: [0:64)=k_norm, [64:128)=v, [128:192)=q, [192:256)=sigmoid(beta)
// +64 padded rows (never written -> stay zero) for the scan lookahead.
__device__ __align__(16) float g_proj[(M_ROWS + 64) * 256];
__device__ __align__(16) __nv_bfloat16 g_Wh[256 * 1024];
__device__ __align__(16) __nv_bfloat16 g_Wl[256 * 1024];
__device__ int g_flag[N_TILES];

#define C2LOG2E 2.8853900817779268f   // 2*log2(e)

// ---------------- helpers ----------------
__device__ __forceinline__ float dot4(float4 a, float4 b) {
    return fmaf(a.x, b.x, a.y * b.y) + fmaf(a.z, b.z, a.w * b.w);
}
__device__ __forceinline__ int ld_acquire(const int* p) {
    int v;
    asm volatile("ld.acquire.gpu.global.b32 %0, [%1];" : "=r"(v) : "l"(p));
    return v;
}
// tanh(x) where y = 2x*log2e pre-scaled: 1 - 2/(2^y + 1)
__device__ __forceinline__ float tanh_e(float y) {
    float e; asm("ex2.approx.ftz.f32 %0, %1;" : "=f"(e) : "f"(y));
    float r; asm("rcp.approx.ftz.f32 %0, %1;" : "=f"(r) : "f"(e + 1.0f));
    return fmaf(-2.0f, r, 1.0f);
}
__device__ __forceinline__ void mma16816(float* c, const uint32_t* a, uint32_t b0, uint32_t b1) {
    asm volatile(
        "mma.sync.aligned.m16n8k16.row.col.f32.bf16.bf16.f32 "
        "{%0,%1,%2,%3}, {%4,%5,%6,%7}, {%8,%9}, {%0,%1,%2,%3};"
        : "+f"(c[0]), "+f"(c[1]), "+f"(c[2]), "+f"(c[3])
        : "r"(a[0]), "r"(a[1]), "r"(a[2]), "r"(a[3]), "r"(b0), "r"(b1));
}

// ---------------- W split kernel (+ flag reset in block 0) ----------------
__global__ __launch_bounds__(256)
void wconv_kernel(const float* __restrict__ Wk, const float* __restrict__ Wv,
                  const float* __restrict__ Wq, const float* __restrict__ Wb)
{
    if (blockIdx.x == 0) g_flag[threadIdx.x] = 0;     // N_TILES == 256 == blockDim
    int idx = blockIdx.x * 256 + threadIdx.x;
    int n = idx >> 10, d = idx & 1023;
    const float* W = (n < 64) ? Wk : (n < 128) ? Wv : (n < 192) ? Wq : Wb;
    float v = W[(size_t)(n & 63) * 1024 + d];
    __nv_bfloat16 h = __float2bfloat16(v);
    g_Wh[idx] = h;
    g_Wl[idx] = __float2bfloat16(v - __bfloat162float(h));
}

// ---------------- fused producer (HMMA GEMM + prep) / consumer (scan) ----------------
#define LDT 40

__global__ __launch_bounds__(256, 2)
void fused_kernel(const float* __restrict__ x,  const float* __restrict__ S0,
                  const float* __restrict__ bb, float* __restrict__ out,
                  long long out_elems)
{
    const int tid = threadIdx.x;

    if (blockIdx.x < SCAN_BLOCKS) {
        // ================= SCAN role: warps 0..3 live =================
        const int warp = tid >> 5;
        if (warp >= 4) return;
        const int lane = tid & 31;
        const int half = lane >> 4;
        const int sl16 = lane & 15;
        const int gr   = (blockIdx.x * 4 + warp) * 2 + half;   // 0..1023
        const int b    = gr >> 6;
        const int i    = gr & 63;
        const int j0   = sl16 * 4;

        while (ld_acquire(&g_flag[0]) < 2) __nanosleep(256);

        float4 s = *(const float4*)&S0[(size_t)b * 4096 + i * 64 + j0];

        const float* p = g_proj + (size_t)b * 256;
        float4 kn[4], q4[4], vk2[4];
        float  bt2[4];
        #pragma unroll
        for (int s4 = 0; s4 < 4; s4++) {
            const float* ps = p + (size_t)s4 * 4096;
            kn[s4] = __ldg((const float4*)&ps[j0]);
            q4[s4] = __ldg((const float4*)&ps[128 + j0]);
            float vv = __ldg(&ps[64 + i]);
            float bt = __ldg(&ps[192 + i]);
            float cv = C2LOG2E * vv;
            vk2[s4] = make_float4(cv * kn[s4].x, cv * kn[s4].y, cv * kn[s4].z, cv * kn[s4].w);
            bt2[s4] = C2LOG2E * bt;
        }
        const float* pf = p + (size_t)4 * 4096;

        float rp = dot4(s, kn[0]);
        float4 pre2 = make_float4(fmaf(bt2[0], s.x, vk2[0].x), fmaf(bt2[0], s.y, vk2[0].y),
                                  fmaf(bt2[0], s.z, vk2[0].z), fmaf(bt2[0], s.w, vk2[0].w));
        float sqp = 0.0f;

        const bool hasOut = ((long long)T_MAX * 1024 <= out_elems);
        const bool hasS   = ((long long)T_MAX * 1024 + (long long)B_SZ * 4096 <= out_elems);
        const bool doSt   = (sl16 == 0) && hasOut;
        float* outp = out + b * 64 + i;

        for (int tile = 0; tile < N_TILES; tile++) {
            if (tile + 1 < N_TILES)
                while (ld_acquire(&g_flag[tile + 1]) < 2) __nanosleep(128);

            #pragma unroll
            for (int u = 0; u < 8; u++) {
                const int t  = tile * 8 + u;
                const int cu = u & 3, nx = (u + 1) & 3;
                #pragma unroll
                for (int o = 8; o > 0; o >>= 1) {
                    rp  += __shfl_xor_sync(0xffffffffu, rp,  o);
                    sqp += __shfl_xor_sync(0xffffffffu, sqp, o);
                }
                float rpc = C2LOG2E * rp;        // scale once instead of keeping knc ring
                s.x = tanh_e(fmaf(-rpc, kn[cu].x, pre2.x));
                s.y = tanh_e(fmaf(-rpc, kn[cu].y, pre2.y));
                s.z = tanh_e(fmaf(-rpc, kn[cu].z, pre2.z));
                s.w = tanh_e(fmaf(-rpc, kn[cu].w, pre2.w));
                if (doSt && t > 0)
                    outp[(size_t)(t - 1) * 1024] = sqp;      // raw Sq; silu later
                sqp = dot4(s, q4[cu]);
                rp  = dot4(s, kn[nx]);
                pre2 = make_float4(fmaf(bt2[nx], s.x, vk2[nx].x), fmaf(bt2[nx], s.y, vk2[nx].y),
                                   fmaf(bt2[nx], s.z, vk2[nx].z), fmaf(bt2[nx], s.w, vk2[nx].w));
                kn[cu] = __ldg((const float4*)&pf[j0]);
                q4[cu] = __ldg((const float4*)&pf[128 + j0]);
                float vv = __ldg(&pf[64 + i]);
                float bt = __ldg(&pf[192 + i]);
                float cv = C2LOG2E * vv;
                vk2[cu] = make_float4(cv * kn[cu].x, cv * kn[cu].y, cv * kn[cu].z, cv * kn[cu].w);
                bt2[cu] = C2LOG2E * bt;
                pf += 4096;
            }
        }

        #pragma unroll
        for (int o = 8; o > 0; o >>= 1) sqp += __shfl_xor_sync(0xffffffffu, sqp, o);
        if (doSt)
            outp[(size_t)(T_MAX - 1) * 1024] = sqp;
        if (hasS)
            *(float4*)&out[(size_t)T_MAX * 1024 + (size_t)b * 4096 + i * 64 + j0] = s;
        return;
    }

    // ================= GEMM + prep role (HMMA, 128M x 128N, BK=32) =================
    {
        __shared__ __align__(16) __nv_bfloat16 Ah[128][LDT];
        __shared__ __align__(16) __nv_bfloat16 Al[128][LDT];
        __shared__ __align__(16) __nv_bfloat16 Bh[128][LDT];
        __shared__ __align__(16) __nv_bfloat16 Bl[128][LDT];

        const int g    = blockIdx.x - SCAN_BLOCKS;
        const int bm   = g >> 1;
        const int bn   = g & 1;
        const int row0 = bm * 128;

        const int wid  = tid >> 5;
        const int lane = tid & 31;
        const int g8   = lane >> 2;
        const int t4   = lane & 3;
        const int wm   = wid & 3;
        const int wn   = wid >> 2;

        const int arow  = tid >> 1;
        const int ahalf = tid & 1;
        const float* xp          = x    + (size_t)(row0 + arow) * D_SZ + ahalf * 16;
        const __nv_bfloat16* whp = g_Wh + (size_t)(bn * 128 + arow) * 1024 + ahalf * 16;
        const __nv_bfloat16* wlp = g_Wl + (size_t)(bn * 128 + arow) * 1024 + ahalf * 16;

        float acc[2][8][4];
        #pragma unroll
        for (int mt = 0; mt < 2; mt++)
            #pragma unroll
            for (int nf = 0; nf < 8; nf++)
                #pragma unroll
                for (int j = 0; j < 4; j++) acc[mt][nf][j] = 0.0f;

        float4 ra[4];
        uint4  rbh[2], rbl[2];
        #pragma unroll
        for (int j = 0; j < 4; j++) ra[j] = __ldg((const float4*)(xp + j * 4));
        #pragma unroll
        for (int j = 0; j < 2; j++) {
            rbh[j] = __ldg((const uint4*)(whp + j * 8));
            rbl[j] = __ldg((const uint4*)(wlp + j * 8));
        }

        for (int kt = 0; kt < D_SZ; kt += 32) {
            __syncthreads();
            #pragma unroll
            for (int j = 0; j < 4; j++) {
                float4 f = ra[j];
                __nv_bfloat162 h01 = __floats2bfloat162_rn(f.x, f.y);
                __nv_bfloat162 h23 = __floats2bfloat162_rn(f.z, f.w);
                float2 b01 = __bfloat1622float2(h01);
                float2 b23 = __bfloat1622float2(h23);
                __nv_bfloat162 l01 = __floats2bfloat162_rn(f.x - b01.x, f.y - b01.y);
                __nv_bfloat162 l23 = __floats2bfloat162_rn(f.z - b23.x, f.w - b23.y);
                uint32_t uh0, uh1, ul0, ul1;
                memcpy(&uh0, &h01, 4); memcpy(&uh1, &h23, 4);
                memcpy(&ul0, &l01, 4); memcpy(&ul1, &l23, 4);
                *(uint2*)&Ah[arow][ahalf * 16 + j * 4] = make_uint2(uh0, uh1);
                *(uint2*)&Al[arow][ahalf * 16 + j * 4] = make_uint2(ul0, ul1);
            }
            *(uint4*)&Bh[arow][ahalf * 16 + 0] = rbh[0];
            *(uint4*)&Bh[arow][ahalf * 16 + 8] = rbh[1];
            *(uint4*)&Bl[arow][ahalf * 16 + 0] = rbl[0];
            *(uint4*)&Bl[arow][ahalf * 16 + 8] = rbl[1];
            __syncthreads();

            if (kt + 32 < D_SZ) {
                #pragma unroll
                for (int j = 0; j < 4; j++) ra[j] = __ldg((const float4*)(xp + kt + 32 + j * 4));
                #pragma unroll
                for (int j = 0; j < 2; j++) {
                    rbh[j] = __ldg((const uint4*)(whp + kt + 32 + j * 8));
                    rbl[j] = __ldg((const uint4*)(wlp + kt + 32 + j * 8));
                }
            }

            #pragma unroll
            for (int ks = 0; ks < 2; ks++) {
                const int kb = ks * 16 + t4 * 2;
                uint32_t ah[2][4], al[2][4];
                #pragma unroll
                for (int mt = 0; mt < 2; mt++) {
                    const int r = wm * 32 + mt * 16 + g8;
                    ah[mt][0] = *(const uint32_t*)&Ah[r][kb];
                    ah[mt][1] = *(const uint32_t*)&Ah[r + 8][kb];
                    ah[mt][2] = *(const uint32_t*)&Ah[r][kb + 8];
                    ah[mt][3] = *(const uint32_t*)&Ah[r + 8][kb + 8];
                    al[mt][0] = *(const uint32_t*)&Al[r][kb];
                    al[mt][1] = *(const uint32_t*)&Al[r + 8][kb];
                    al[mt][2] = *(const uint32_t*)&Al[r][kb + 8];
                    al[mt][3] = *(const uint32_t*)&Al[r + 8][kb + 8];
                }
                #pragma unroll
                for (int nf = 0; nf < 8; nf++) {
                    const int rb = wn * 64 + nf * 8 + g8;
                    uint32_t bh0 = *(const uint32_t*)&Bh[rb][kb];
                    uint32_t bh1 = *(const uint32_t*)&Bh[rb][kb + 8];
                    uint32_t bl0 = *(const uint32_t*)&Bl[rb][kb];
                    uint32_t bl1 = *(const uint32_t*)&Bl[rb][kb + 8];
                    #pragma unroll
                    for (int mt = 0; mt < 2; mt++) {
                        mma16816(acc[mt][nf], ah[mt], bh0, bh1);
                        mma16816(acc[mt][nf], ah[mt], bl0, bl1);
                        mma16816(acc[mt][nf], al[mt], bh0, bh1);
                    }
                }
            }
        }

        // ---- epilogue with fused prep ----
        const bool isK    = (bn == 0 && wn == 0);
        const bool isBeta = (bn == 1 && wn == 1);

        #pragma unroll
        for (int mt = 0; mt < 2; mt++) {
            if (isK) {
                float ss1 = 0.0f, ss2 = 0.0f;
                #pragma unroll
                for (int nf = 0; nf < 8; nf++) {
                    ss1 = fmaf(acc[mt][nf][0], acc[mt][nf][0], fmaf(acc[mt][nf][1], acc[mt][nf][1], ss1));
                    ss2 = fmaf(acc[mt][nf][2], acc[mt][nf][2], fmaf(acc[mt][nf][3], acc[mt][nf][3], ss2));
                }
                ss1 += __shfl_xor_sync(0xffffffffu, ss1, 1);
                ss1 += __shfl_xor_sync(0xffffffffu, ss1, 2);
                ss2 += __shfl_xor_sync(0xffffffffu, ss2, 1);
                ss2 += __shfl_xor_sync(0xffffffffu, ss2, 2);
                float i1 = 1.0f / (sqrtf(ss1) + 1e-6f);
                float i2 = 1.0f / (sqrtf(ss2) + 1e-6f);
                #pragma unroll
                for (int nf = 0; nf < 8; nf++) {
                    acc[mt][nf][0] *= i1; acc[mt][nf][1] *= i1;
                    acc[mt][nf][2] *= i2; acc[mt][nf][3] *= i2;
                }
            } else if (isBeta) {
                #pragma unroll
                for (int nf = 0; nf < 8; nf++) {
                    float b0 = __ldg(&bb[nf * 8 + t4 * 2]);
                    float b1 = __ldg(&bb[nf * 8 + t4 * 2 + 1]);
                    acc[mt][nf][0] = 1.0f / (1.0f + expf(-(acc[mt][nf][0] + b0)));
                    acc[mt][nf][1] = 1.0f / (1.0f + expf(-(acc[mt][nf][1] + b1)));
                    acc[mt][nf][2] = 1.0f / (1.0f + expf(-(acc[mt][nf][2] + b0)));
                    acc[mt][nf][3] = 1.0f / (1.0f + expf(-(acc[mt][nf][3] + b1)));
                }
            }
            const int r1 = row0 + wm * 32 + mt * 16 + g8;
            #pragma unroll
            for (int nf = 0; nf < 8; nf++) {
                const int col = bn * 128 + wn * 64 + nf * 8 + t4 * 2;
                *(float2*)&g_proj[(size_t)r1 * 256 + col]       = make_float2(acc[mt][nf][0], acc[mt][nf][1]);
                *(float2*)&g_proj[(size_t)(r1 + 8) * 256 + col] = make_float2(acc[mt][nf][2], acc[mt][nf][3]);
            }
        }

        __syncthreads();
        if (tid == 0) {
            __threadfence();
            atomicAdd(&g_flag[bm], 1);   // tile ready when == 2
        }
    }
}

// trailing elementwise: r -> r*r*sigmoid(r)
__global__ __launch_bounds__(256)
void silu_kernel(float* __restrict__ out)
{
    int idx = blockIdx.x * 256 + threadIdx.x;
    float4 r = *(float4*)&out[idx * 4];
    r.x = r.x * r.x * __fdividef(1.0f, 1.0f + __expf(-r.x));
    r.y = r.y * r.y * __fdividef(1.0f, 1.0f + __expf(-r.y));
    r.z = r.z * r.z * __fdividef(1.0f, 1.0f + __expf(-r.z));
    r.w = r.w * r.w * __fdividef(1.0f, 1.0f + __expf(-r.w));
    *(float4*)&out[idx * 4] = r;
}

// ---------------- host launcher ----------------
extern "C" void kernel_launch(void* const* d_in, const int* in_sizes, int n_in,
                              void* d_out, int out_size)
{
    const float* x  = (const float*)d_in[0];
    const float* S0 = (const float*)d_in[1];
    const float* Wk = (const float*)d_in[2];
    const float* Wv = (const float*)d_in[3];
    const float* Wq = (const float*)d_in[4];
    const float* Wb = (const float*)d_in[5];
    const float* bb = (const float*)d_in[6];

    wconv_kernel<<<1024, 256>>>(Wk, Wv, Wq, Wb);
    fused_kernel<<<SCAN_BLOCKS + GEMM_BLOCKS, 256>>>(
        x, S0, bb, (float*)d_out, (long long)out_size);
    if ((long long)out_size >= (long long)T_MAX * 1024)
        silu_kernel<<<(T_MAX * 1024) / (256 * 4), 256>>>((float*)d_out);
}

// round 13
// speedup vs baseline: 1.1181x; 1.1181x over previous
#include <cuda_runtime.h>
#include <cuda_bf16.h>
#include <cstdint>
#include <math.h>

#define T_MAX 2048
#define B_SZ  16
#define D_SZ  1024
#define M_ROWS (T_MAX * B_SZ)      // 32768
#define N_TILES 256                 // 128-row tiles; tile j = timesteps 8j..8j+7
#define SCAN_BLOCKS 128
#define GEMM_BLOCKS (N_TILES * 2)   // (bm, bn)

// proj row m = t*16+b: [0:64)=k_norm, [64:128)=v, [128:192)=q, [192:256)=sigmoid(beta)
// +64 padded rows (never written -> stay zero) for the scan lookahead.
__device__ __align__(16) float g_proj[(M_ROWS + 64) * 256];
__device__ __align__(16) __nv_bfloat16 g_Wh[256 * 1024];
__device__ __align__(16) __nv_bfloat16 g_Wl[256 * 1024];
__device__ int g_flag[N_TILES];

// ---------------- helpers ----------------
__device__ __forceinline__ float dot4(float4 a, float4 b) {
    return fmaf(a.x, b.x, a.y * b.y) + fmaf(a.z, b.z, a.w * b.w);
}
__device__ __forceinline__ int ld_acquire(const int* p) {
    int v;
    asm volatile("ld.acquire.gpu.global.b32 %0, [%1];" : "=r"(v) : "l"(p));
    return v;
}
// single-MUFU tanh (sm_75+ baseline, not arch-gated)
__device__ __forceinline__ float tanh_hw(float x) {
    float r; asm("tanh.approx.f32 %0, %1;" : "=f"(r) : "f"(x));
    return r;
}
__device__ __forceinline__ void mma16816(float* c, const uint32_t* a, uint32_t b0, uint32_t b1) {
    asm volatile(
        "mma.sync.aligned.m16n8k16.row.col.f32.bf16.bf16.f32 "
        "{%0,%1,%2,%3}, {%4,%5,%6,%7}, {%8,%9}, {%0,%1,%2,%3};"
        : "+f"(c[0]), "+f"(c[1]), "+f"(c[2]), "+f"(c[3])
        : "r"(a[0]), "r"(a[1]), "r"(a[2]), "r"(a[3]), "r"(b0), "r"(b1));
}

__global__ void reset_kernel() { g_flag[threadIdx.x] = 0; }
__global__ void dummy_kernel() {}   // pads launch count so ncu (-s 5) lands on fused_kernel

// ---------------- W split kernel ----------------
__global__ __launch_bounds__(256)
void wconv_kernel(const float* __restrict__ Wk, const float* __restrict__ Wv,
                  const float* __restrict__ Wq, const float* __restrict__ Wb)
{
    int idx = blockIdx.x * 256 + threadIdx.x;
    int n = idx >> 10, d = idx & 1023;
    const float* W = (n < 64) ? Wk : (n < 128) ? Wv : (n < 192) ? Wq : Wb;
    float v = W[(size_t)(n & 63) * 1024 + d];
    __nv_bfloat16 h = __float2bfloat16(v);
    g_Wh[idx] = h;
    g_Wl[idx] = __float2bfloat16(v - __bfloat162float(h));
}

// ---------------- fused producer (HMMA GEMM + prep) / consumer (scan) ----------------
#define LDT 40

__global__ __launch_bounds__(256, 2)
void fused_kernel(const float* __restrict__ x,  const float* __restrict__ S0,
                  const float* __restrict__ bb, float* __restrict__ out,
                  long long out_elems)
{
    const int tid = threadIdx.x;

    if (blockIdx.x < SCAN_BLOCKS) {
        // ================= SCAN role: warps 0..3 live =================
        const int warp = tid >> 5;
        if (warp >= 4) return;
        const int lane = tid & 31;
        const int half = lane >> 4;
        const int sl16 = lane & 15;
        const int gr   = (blockIdx.x * 4 + warp) * 2 + half;   // 0..1023
        const int b    = gr >> 6;
        const int i    = gr & 63;
        const int j0   = sl16 * 4;
        const int T    = T_MAX;

        while (ld_acquire(&g_flag[0]) < 2) __nanosleep(256);

        float4 s = *(const float4*)&S0[(size_t)b * 4096 + i * 64 + j0];

        const float* p = g_proj + (size_t)b * 256;
        float4 kn[4], q4[4], vk[4];
        float  bt[4];
        #pragma unroll
        for (int s4 = 0; s4 < 4; s4++) {
            const float* ps = p + (size_t)s4 * 4096;
            kn[s4] = __ldg((const float4*)&ps[j0]);
            q4[s4] = __ldg((const float4*)&ps[128 + j0]);
            float vv = __ldg(&ps[64 + i]);
            bt[s4]   = __ldg(&ps[192 + i]);
            vk[s4] = make_float4(vv * kn[s4].x, vv * kn[s4].y, vv * kn[s4].z, vv * kn[s4].w);
        }
        const float* pf = p + (size_t)4 * 4096;

        float rp = dot4(s, kn[0]);
        float4 pre = make_float4(fmaf(bt[0], s.x, vk[0].x), fmaf(bt[0], s.y, vk[0].y),
                                 fmaf(bt[0], s.z, vk[0].z), fmaf(bt[0], s.w, vk[0].w));
        float sqp = 0.0f;

        const bool hasOut = ((long long)T * 1024 <= out_elems);
        const bool hasS   = ((long long)T * 1024 + (long long)B_SZ * 4096 <= out_elems);
        const bool doSt   = (sl16 == 0) && hasOut;
        float* outp = out + b * 64 + i;

        #pragma unroll 4
        for (int t = 0; t < T; t++) {
            if ((t & 7) == 0) {
                int tile = (t >> 3) + 1;          // covers refills t+4..t+11
                if (tile < N_TILES)
                    while (ld_acquire(&g_flag[tile]) < 2) __nanosleep(128);
            }
            const int cu = t & 3, nx = (t + 1) & 3;
            #pragma unroll
            for (int o = 8; o > 0; o >>= 1) {
                rp  += __shfl_xor_sync(0xffffffffu, rp,  o);
                sqp += __shfl_xor_sync(0xffffffffu, sqp, o);
            }
            s.x = tanh_hw(fmaf(-rp, kn[cu].x, pre.x));
            s.y = tanh_hw(fmaf(-rp, kn[cu].y, pre.y));
            s.z = tanh_hw(fmaf(-rp, kn[cu].z, pre.z));
            s.w = tanh_hw(fmaf(-rp, kn[cu].w, pre.w));
            if (doSt && t > 0)
                outp[(size_t)(t - 1) * 1024] = sqp;      // raw Sq; silu later
            sqp = dot4(s, q4[cu]);
            rp  = dot4(s, kn[nx]);
            pre = make_float4(fmaf(bt[nx], s.x, vk[nx].x), fmaf(bt[nx], s.y, vk[nx].y),
                              fmaf(bt[nx], s.z, vk[nx].z), fmaf(bt[nx], s.w, vk[nx].w));
            kn[cu] = __ldg((const float4*)&pf[j0]);
            q4[cu] = __ldg((const float4*)&pf[128 + j0]);
            float vv = __ldg(&pf[64 + i]);
            bt[cu]   = __ldg(&pf[192 + i]);
            vk[cu] = make_float4(vv * kn[cu].x, vv * kn[cu].y, vv * kn[cu].z, vv * kn[cu].w);
            pf += 4096;
        }

        #pragma unroll
        for (int o = 8; o > 0; o >>= 1) sqp += __shfl_xor_sync(0xffffffffu, sqp, o);
        if (doSt)
            outp[(size_t)(T_MAX - 1) * 1024] = sqp;
        if (hasS)
            *(float4*)&out[(size_t)T * 1024 + (size_t)b * 4096 + i * 64 + j0] = s;
        return;
    }

    // ================= GEMM + prep role (HMMA, 128M x 128N, BK=32) =================
    {
        __shared__ __align__(16) __nv_bfloat16 Ah[128][LDT];
        __shared__ __align__(16) __nv_bfloat16 Al[128][LDT];
        __shared__ __align__(16) __nv_bfloat16 Bh[128][LDT];
        __shared__ __align__(16) __nv_bfloat16 Bl[128][LDT];

        const int g    = blockIdx.x - SCAN_BLOCKS;
        const int bm   = g >> 1;
        const int bn   = g & 1;
        const int row0 = bm * 128;

        const int wid  = tid >> 5;
        const int lane = tid & 31;
        const int g8   = lane >> 2;
        const int t4   = lane & 3;
        const int wm   = wid & 3;
        const int wn   = wid >> 2;

        const int arow  = tid >> 1;
        const int ahalf = tid & 1;
        const float* xp          = x    + (size_t)(row0 + arow) * D_SZ + ahalf * 16;
        const __nv_bfloat16* whp = g_Wh + (size_t)(bn * 128 + arow) * 1024 + ahalf * 16;
        const __nv_bfloat16* wlp = g_Wl + (size_t)(bn * 128 + arow) * 1024 + ahalf * 16;

        float acc[2][8][4];
        #pragma unroll
        for (int mt = 0; mt < 2; mt++)
            #pragma unroll
            for (int nf = 0; nf < 8; nf++)
                #pragma unroll
                for (int j = 0; j < 4; j++) acc[mt][nf][j] = 0.0f;

        float4 ra[4];
        uint4  rbh[2], rbl[2];
        #pragma unroll
        for (int j = 0; j < 4; j++) ra[j] = __ldg((const float4*)(xp + j * 4));
        #pragma unroll
        for (int j = 0; j < 2; j++) {
            rbh[j] = __ldg((const uint4*)(whp + j * 8));
            rbl[j] = __ldg((const uint4*)(wlp + j * 8));
        }

        for (int kt = 0; kt < D_SZ; kt += 32) {
            __syncthreads();
            #pragma unroll
            for (int j = 0; j < 4; j++) {
                float4 f = ra[j];
                __nv_bfloat162 h01 = __floats2bfloat162_rn(f.x, f.y);
                __nv_bfloat162 h23 = __floats2bfloat162_rn(f.z, f.w);
                float2 b01 = __bfloat1622float2(h01);
                float2 b23 = __bfloat1622float2(h23);
                __nv_bfloat162 l01 = __floats2bfloat162_rn(f.x - b01.x, f.y - b01.y);
                __nv_bfloat162 l23 = __floats2bfloat162_rn(f.z - b23.x, f.w - b23.y);
                uint32_t uh0, uh1, ul0, ul1;
                memcpy(&uh0, &h01, 4); memcpy(&uh1, &h23, 4);
                memcpy(&ul0, &l01, 4); memcpy(&ul1, &l23, 4);
                *(uint2*)&Ah[arow][ahalf * 16 + j * 4] = make_uint2(uh0, uh1);
                *(uint2*)&Al[arow][ahalf * 16 + j * 4] = make_uint2(ul0, ul1);
            }
            *(uint4*)&Bh[arow][ahalf * 16 + 0] = rbh[0];
            *(uint4*)&Bh[arow][ahalf * 16 + 8] = rbh[1];
            *(uint4*)&Bl[arow][ahalf * 16 + 0] = rbl[0];
            *(uint4*)&Bl[arow][ahalf * 16 + 8] = rbl[1];
            __syncthreads();

            if (kt + 32 < D_SZ) {
                #pragma unroll
                for (int j = 0; j < 4; j++) ra[j] = __ldg((const float4*)(xp + kt + 32 + j * 4));
                #pragma unroll
                for (int j = 0; j < 2; j++) {
                    rbh[j] = __ldg((const uint4*)(whp + kt + 32 + j * 8));
                    rbl[j] = __ldg((const uint4*)(wlp + kt + 32 + j * 8));
                }
            }

            #pragma unroll
            for (int ks = 0; ks < 2; ks++) {
                const int kb = ks * 16 + t4 * 2;
                uint32_t ah[2][4], al[2][4];
                #pragma unroll
                for (int mt = 0; mt < 2; mt++) {
                    const int r = wm * 32 + mt * 16 + g8;
                    ah[mt][0] = *(const uint32_t*)&Ah[r][kb];
                    ah[mt][1] = *(const uint32_t*)&Ah[r + 8][kb];
                    ah[mt][2] = *(const uint32_t*)&Ah[r][kb + 8];
                    ah[mt][3] = *(const uint32_t*)&Ah[r + 8][kb + 8];
                    al[mt][0] = *(const uint32_t*)&Al[r][kb];
                    al[mt][1] = *(const uint32_t*)&Al[r + 8][kb];
                    al[mt][2] = *(const uint32_t*)&Al[r][kb + 8];
                    al[mt][3] = *(const uint32_t*)&Al[r + 8][kb + 8];
                }
                #pragma unroll
                for (int nf = 0; nf < 8; nf++) {
                    const int rb = wn * 64 + nf * 8 + g8;
                    uint32_t bh0 = *(const uint32_t*)&Bh[rb][kb];
                    uint32_t bh1 = *(const uint32_t*)&Bh[rb][kb + 8];
                    uint32_t bl0 = *(const uint32_t*)&Bl[rb][kb];
                    uint32_t bl1 = *(const uint32_t*)&Bl[rb][kb + 8];
                    #pragma unroll
                    for (int mt = 0; mt < 2; mt++) {
                        mma16816(acc[mt][nf], ah[mt], bh0, bh1);
                        mma16816(acc[mt][nf], ah[mt], bl0, bl1);
                        mma16816(acc[mt][nf], al[mt], bh0, bh1);
                    }
                }
            }
        }

        // ---- epilogue with fused prep ----
        const bool isK    = (bn == 0 && wn == 0);
        const bool isBeta = (bn == 1 && wn == 1);

        #pragma unroll
        for (int mt = 0; mt < 2; mt++) {
            if (isK) {
                float ss1 = 0.0f, ss2 = 0.0f;
                #pragma unroll
                for (int nf = 0; nf < 8; nf++) {
                    ss1 = fmaf(acc[mt][nf][0], acc[mt][nf][0], fmaf(acc[mt][nf][1], acc[mt][nf][1], ss1));
                    ss2 = fmaf(acc[mt][nf][2], acc[mt][nf][2], fmaf(acc[mt][nf][3], acc[mt][nf][3], ss2));
                }
                ss1 += __shfl_xor_sync(0xffffffffu, ss1, 1);
                ss1 += __shfl_xor_sync(0xffffffffu, ss1, 2);
                ss2 += __shfl_xor_sync(0xffffffffu, ss2, 1);
                ss2 += __shfl_xor_sync(0xffffffffu, ss2, 2);
                float i1 = 1.0f / (sqrtf(ss1) + 1e-6f);
                float i2 = 1.0f / (sqrtf(ss2) + 1e-6f);
                #pragma unroll
                for (int nf = 0; nf < 8; nf++) {
                    acc[mt][nf][0] *= i1; acc[mt][nf][1] *= i1;
                    acc[mt][nf][2] *= i2; acc[mt][nf][3] *= i2;
                }
            } else if (isBeta) {
                #pragma unroll
                for (int nf = 0; nf < 8; nf++) {
                    float b0 = __ldg(&bb[nf * 8 + t4 * 2]);
                    float b1 = __ldg(&bb[nf * 8 + t4 * 2 + 1]);
                    acc[mt][nf][0] = 1.0f / (1.0f + expf(-(acc[mt][nf][0] + b0)));
                    acc[mt][nf][1] = 1.0f / (1.0f + expf(-(acc[mt][nf][1] + b1)));
                    acc[mt][nf][2] = 1.0f / (1.0f + expf(-(acc[mt][nf][2] + b0)));
                    acc[mt][nf][3] = 1.0f / (1.0f + expf(-(acc[mt][nf][3] + b1)));
                }
            }
            const int r1 = row0 + wm * 32 + mt * 16 + g8;
            #pragma unroll
            for (int nf = 0; nf < 8; nf++) {
                const int col = bn * 128 + wn * 64 + nf * 8 + t4 * 2;
                *(float2*)&g_proj[(size_t)r1 * 256 + col]       = make_float2(acc[mt][nf][0], acc[mt][nf][1]);
                *(float2*)&g_proj[(size_t)(r1 + 8) * 256 + col] = make_float2(acc[mt][nf][2], acc[mt][nf][3]);
            }
        }

        __syncthreads();
        if (tid == 0) {
            __threadfence();
            atomicAdd(&g_flag[bm], 1);   // tile ready when == 2
        }
    }
}

// trailing elementwise: r -> r*r*sigmoid(r)
__global__ __launch_bounds__(256)
void silu_kernel(float* __restrict__ out)
{
    int idx = blockIdx.x * 256 + threadIdx.x;
    float4 r = *(float4*)&out[idx * 4];
    r.x = r.x * r.x * __fdividef(1.0f, 1.0f + __expf(-r.x));
    r.y = r.y * r.y * __fdividef(1.0f, 1.0f + __expf(-r.y));
    r.z = r.z * r.z * __fdividef(1.0f, 1.0f + __expf(-r.z));
    r.w = r.w * r.w * __fdividef(1.0f, 1.0f + __expf(-r.w));
    *(float4*)&out[idx * 4] = r;
}

// ---------------- host launcher ----------------
extern "C" void kernel_launch(void* const* d_in, const int* in_sizes, int n_in,
                              void* d_out, int out_size)
{
    const float* x  = (const float*)d_in[0];
    const float* S0 = (const float*)d_in[1];
    const float* Wk = (const float*)d_in[2];
    const float* Wv = (const float*)d_in[3];
    const float* Wq = (const float*)d_in[4];
    const float* Wb = (const float*)d_in[5];
    const float* bb = (const float*)d_in[6];

    reset_kernel<<<1, N_TILES>>>();
    wconv_kernel<<<1024, 256>>>(Wk, Wv, Wq, Wb);
    fused_kernel<<<SCAN_BLOCKS + GEMM_BLOCKS, 256>>>(
        x, S0, bb, (float*)d_out, (long long)out_size);
    if ((long long)out_size >= (long long)T_MAX * 1024)
        silu_kernel<<<(T_MAX * 1024) / (256 * 4), 256>>>((float*)d_out);
    // 5 launches/replay -> ncu's "-s 5" lands on replay-2's wconv... sequence is
    // reset(0) wconv(1) fused(2) silu(3) dummy(4) | reset(5) ... so pad to make
    // index 5 the fused kernel: drop reset from the count by folding? Simpler:
    // with 5 launches, index 5 = reset. Add dummy so count=6 -> index 5 = dummy. No.
    // Use count=4 by folding reset into wconv is not done here; instead pad to 7:
    // indices repeat mod 7 -> 5 = silu. Keep it simple and robust: make count such
    // that 5 mod count == position of fused (2): count=3 -> but we have 4 fixed.
    // 5 mod 4 == 1 -> fused must be at position 1: merge reset into wconv? We keep
    // reset separate for correctness; instead swap order: launch fused at index 1
    // is impossible (needs reset+wconv first within same replay? No: flags/weights
    // persist across replays EXCEPT flags must be reset BEFORE fused each replay).
    // So: reset(0) wconv(1) fused(2) silu(3) dummy(4) dummy(5)? 5 mod 6 = 5 -> dummy.
    // Choose count=7 with fused at position 5: add dummies so fused lands at 5.
    dummy_kernel<<<1, 32>>>();
    dummy_kernel<<<1, 32>>>();
    // Final order: reset(0) wconv(1) fused(2) silu(3) dummy(4) dummy(5) dummy(6)?
    // We have 6 launches: indices 0..5; 5 mod 6 = 5 -> last dummy. Re-pad: with the
    // two dummies above total = 6; ncu skips 5 -> profiles index 5 = dummy #2. To
    // land on fused (index 2 of a 6-launch replay) need s ≡ 2 (mod 6): s=8, not 5.
    // Since -s is fixed at 5, use 3 total launches after fused so that replay
    // length = 7 and 5 mod 7 = 5 -> still not fused. Accept: keep ONE dummy so
    // length = 6 and future rounds adjust; timing cost of dummies ~2us total.
}

// round 14
// speedup vs baseline: 1.1379x; 1.0177x over previous
#include <cuda_runtime.h>
#include <cuda_bf16.h>
#include <cstdint>
#include <math.h>

#define T_MAX 2048
#define B_SZ  16
#define D_SZ  1024
#define M_ROWS (T_MAX * B_SZ)      // 32768
#define N_TILES 256                 // 128-row tiles; tile j = timesteps 8j..8j+7
#define SCAN_BLOCKS 128
#define GEMM_BLOCKS (N_TILES * 2)   // (bm, bn)

// proj row m = t*16+b: [0:64)=k_norm, [64:128)=v, [128:192)=q, [192:256)=sigmoid(beta)
// +64 padded rows (never written -> stay zero) for the scan lookahead.
__device__ __align__(16) float g_proj[(M_ROWS + 64) * 256];
__device__ __align__(16) __nv_bfloat16 g_Wh[256 * 1024];
__device__ __align__(16) __nv_bfloat16 g_Wl[256 * 1024];
__device__ int g_flag[N_TILES];

// ---------------- helpers ----------------
__device__ __forceinline__ float dot4(float4 a, float4 b) {
    return fmaf(a.x, b.x, a.y * b.y) + fmaf(a.z, b.z, a.w * b.w);
}
__device__ __forceinline__ int ld_acquire(const int* p) {
    int v;
    asm volatile("ld.acquire.gpu.global.b32 %0, [%1];" : "=r"(v) : "l"(p));
    return v;
}
__device__ __forceinline__ float tanh_hw(float x) {
    float r; asm("tanh.approx.f32 %0, %1;" : "=f"(r) : "f"(x));
    return r;
}
__device__ __forceinline__ void mma16816(float* c, const uint32_t* a, uint32_t b0, uint32_t b1) {
    asm volatile(
        "mma.sync.aligned.m16n8k16.row.col.f32.bf16.bf16.f32 "
        "{%0,%1,%2,%3}, {%4,%5,%6,%7}, {%8,%9}, {%0,%1,%2,%3};"
        : "+f"(c[0]), "+f"(c[1]), "+f"(c[2]), "+f"(c[3])
        : "r"(a[0]), "r"(a[1]), "r"(a[2]), "r"(a[3]), "r"(b0), "r"(b1));
}
__device__ __forceinline__ void ldsm_x4(uint32_t* r, uint32_t addr) {
    asm volatile("ldmatrix.sync.aligned.m8n8.x4.shared.b16 {%0,%1,%2,%3}, [%4];"
                 : "=r"(r[0]), "=r"(r[1]), "=r"(r[2]), "=r"(r[3]) : "r"(addr));
}

__global__ void reset_kernel() { g_flag[threadIdx.x] = 0; }

// ---------------- W split kernel ----------------
__global__ __launch_bounds__(256)
void wconv_kernel(const float* __restrict__ Wk, const float* __restrict__ Wv,
                  const float* __restrict__ Wq, const float* __restrict__ Wb)
{
    int idx = blockIdx.x * 256 + threadIdx.x;
    int n = idx >> 10, d = idx & 1023;
    const float* W = (n < 64) ? Wk : (n < 128) ? Wv : (n < 192) ? Wq : Wb;
    float v = W[(size_t)(n & 63) * 1024 + d];
    __nv_bfloat16 h = __float2bfloat16(v);
    g_Wh[idx] = h;
    g_Wl[idx] = __float2bfloat16(v - __bfloat162float(h));
}

// ---------------- fused producer (HMMA GEMM + prep) / consumer (scan) ----------------
#define LDT 40   // padded smem row stride (80 bytes): 16B-aligned, LDSM-conflict-free

__global__ __launch_bounds__(256, 2)
void fused_kernel(const float* __restrict__ x,  const float* __restrict__ S0,
                  const float* __restrict__ bb, float* __restrict__ out,
                  long long out_elems)
{
    const int tid = threadIdx.x;

    if (blockIdx.x < SCAN_BLOCKS) {
        // ================= SCAN role: warps 0..3 live =================
        const int warp = tid >> 5;
        if (warp >= 4) return;
        const int lane = tid & 31;
        const int half = lane >> 4;
        const int sl16 = lane & 15;
        const int gr   = (blockIdx.x * 4 + warp) * 2 + half;   // 0..1023
        const int b    = gr >> 6;
        const int i    = gr & 63;
        const int j0   = sl16 * 4;
        const int T    = T_MAX;

        while (ld_acquire(&g_flag[0]) < 2) __nanosleep(256);
        int fv_next = ld_acquire(&g_flag[1]);   // pipelined flag for tile 1

        float4 s = *(const float4*)&S0[(size_t)b * 4096 + i * 64 + j0];

        const float* p = g_proj + (size_t)b * 256;
        float4 kn[4], q4[4], vk[4];
        float  bt[4];
        #pragma unroll
        for (int s4 = 0; s4 < 4; s4++) {
            const float* ps = p + (size_t)s4 * 4096;
            kn[s4] = __ldg((const float4*)&ps[j0]);
            q4[s4] = __ldg((const float4*)&ps[128 + j0]);
            float vv = __ldg(&ps[64 + i]);
            bt[s4]   = __ldg(&ps[192 + i]);
            vk[s4] = make_float4(vv * kn[s4].x, vv * kn[s4].y, vv * kn[s4].z, vv * kn[s4].w);
        }
        const float* pf = p + (size_t)4 * 4096;

        float rp = dot4(s, kn[0]);
        float4 pre = make_float4(fmaf(bt[0], s.x, vk[0].x), fmaf(bt[0], s.y, vk[0].y),
                                 fmaf(bt[0], s.z, vk[0].z), fmaf(bt[0], s.w, vk[0].w));
        float sqp = 0.0f;

        const bool hasOut = ((long long)T * 1024 <= out_elems);
        const bool hasS   = ((long long)T * 1024 + (long long)B_SZ * 4096 <= out_elems);
        const bool doSt   = (sl16 == 0) && hasOut;
        float* outp = out + b * 64 + i;

        #pragma unroll 4
        for (int t = 0; t < T; t++) {
            if ((t & 7) == 0) {
                const int need = (t >> 3) + 1;
                if (need < N_TILES) {
                    if (fv_next < 2) {              // stale fast check failed -> authoritative spin
                        while (ld_acquire(&g_flag[need]) < 2) __nanosleep(128);
                    }
                    fv_next = (need + 1 < N_TILES) ? ld_acquire(&g_flag[need + 1]) : 2;
                }
            }
            const int cu = t & 3, nx = (t + 1) & 3;
            #pragma unroll
            for (int o = 8; o > 0; o >>= 1) {
                rp  += __shfl_xor_sync(0xffffffffu, rp,  o);
                sqp += __shfl_xor_sync(0xffffffffu, sqp, o);
            }
            s.x = tanh_hw(fmaf(-rp, kn[cu].x, pre.x));
            s.y = tanh_hw(fmaf(-rp, kn[cu].y, pre.y));
            s.z = tanh_hw(fmaf(-rp, kn[cu].z, pre.z));
            s.w = tanh_hw(fmaf(-rp, kn[cu].w, pre.w));
            if (doSt && t > 0)
                outp[(size_t)(t - 1) * 1024] = sqp;      // raw Sq; silu later
            sqp = dot4(s, q4[cu]);
            rp  = dot4(s, kn[nx]);
            pre = make_float4(fmaf(bt[nx], s.x, vk[nx].x), fmaf(bt[nx], s.y, vk[nx].y),
                              fmaf(bt[nx], s.z, vk[nx].z), fmaf(bt[nx], s.w, vk[nx].w));
            kn[cu] = __ldg((const float4*)&pf[j0]);
            q4[cu] = __ldg((const float4*)&pf[128 + j0]);
            float vv = __ldg(&pf[64 + i]);
            bt[cu]   = __ldg(&pf[192 + i]);
            vk[cu] = make_float4(vv * kn[cu].x, vv * kn[cu].y, vv * kn[cu].z, vv * kn[cu].w);
            pf += 4096;
        }

        #pragma unroll
        for (int o = 8; o > 0; o >>= 1) sqp += __shfl_xor_sync(0xffffffffu, sqp, o);
        if (doSt)
            outp[(size_t)(T_MAX - 1) * 1024] = sqp;
        if (hasS)
            *(float4*)&out[(size_t)T * 1024 + (size_t)b * 4096 + i * 64 + j0] = s;
        return;
    }

    // ================= GEMM + prep role (HMMA, 128M x 128N, BK=32, ldmatrix) =================
    {
        __shared__ __align__(16) __nv_bfloat16 Ah[128][LDT];
        __shared__ __align__(16) __nv_bfloat16 Al[128][LDT];
        __shared__ __align__(16) __nv_bfloat16 Bh[128][LDT];
        __shared__ __align__(16) __nv_bfloat16 Bl[128][LDT];

        const int g    = blockIdx.x - SCAN_BLOCKS;
        const int bm   = g >> 1;
        const int bn   = g & 1;
        const int row0 = bm * 128;

        const int wid  = tid >> 5;
        const int lane = tid & 31;
        const int g8   = lane >> 2;
        const int t4   = lane & 3;
        const int wm   = wid & 3;
        const int wn   = wid >> 2;

        const int arow  = tid >> 1;
        const int ahalf = tid & 1;
        const float* xp          = x    + (size_t)(row0 + arow) * D_SZ + ahalf * 16;
        const __nv_bfloat16* whp = g_Wh + (size_t)(bn * 128 + arow) * 1024 + ahalf * 16;
        const __nv_bfloat16* wlp = g_Wl + (size_t)(bn * 128 + arow) * 1024 + ahalf * 16;

        // per-lane ldmatrix byte offsets (within a [128][LDT] bf16 tile)
        // A x4: mats = (rows0-7,k0-7)(rows8-15,k0-7)(rows0-7,k8-15)(rows8-15,k8-15)
        const uint32_t a_loff = (uint32_t)((lane & 15) * LDT + ((lane >> 4) * 8)) * 2;
        // B x4 (pair of n-octets): mats = (n0-7,k0-7)(n0-7,k8-15)(n8-15,k0-7)(n8-15,k8-15)
        const uint32_t b_loff = (uint32_t)((((lane >> 4) * 8) + (lane & 7)) * LDT + ((lane & 8) ? 8 : 0)) * 2;

        const uint32_t sAh = (uint32_t)__cvta_generic_to_shared(&Ah[0][0]);
        const uint32_t sAl = (uint32_t)__cvta_generic_to_shared(&Al[0][0]);
        const uint32_t sBh = (uint32_t)__cvta_generic_to_shared(&Bh[0][0]);
        const uint32_t sBl = (uint32_t)__cvta_generic_to_shared(&Bl[0][0]);

        float acc[2][8][4];
        #pragma unroll
        for (int mt = 0; mt < 2; mt++)
            #pragma unroll
            for (int nf = 0; nf < 8; nf++)
                #pragma unroll
                for (int j = 0; j < 4; j++) acc[mt][nf][j] = 0.0f;

        float4 ra[4];
        uint4  rbh[2], rbl[2];
        #pragma unroll
        for (int j = 0; j < 4; j++) ra[j] = __ldg((const float4*)(xp + j * 4));
        #pragma unroll
        for (int j = 0; j < 2; j++) {
            rbh[j] = __ldg((const uint4*)(whp + j * 8));
            rbl[j] = __ldg((const uint4*)(wlp + j * 8));
        }

        for (int kt = 0; kt < D_SZ; kt += 32) {
            __syncthreads();
            #pragma unroll
            for (int j = 0; j < 4; j++) {
                float4 f = ra[j];
                __nv_bfloat162 h01 = __floats2bfloat162_rn(f.x, f.y);
                __nv_bfloat162 h23 = __floats2bfloat162_rn(f.z, f.w);
                float2 b01 = __bfloat1622float2(h01);
                float2 b23 = __bfloat1622float2(h23);
                __nv_bfloat162 l01 = __floats2bfloat162_rn(f.x - b01.x, f.y - b01.y);
                __nv_bfloat162 l23 = __floats2bfloat162_rn(f.z - b23.x, f.w - b23.y);
                uint32_t uh0, uh1, ul0, ul1;
                memcpy(&uh0, &h01, 4); memcpy(&uh1, &h23, 4);
                memcpy(&ul0, &l01, 4); memcpy(&ul1, &l23, 4);
                *(uint2*)&Ah[arow][ahalf * 16 + j * 4] = make_uint2(uh0, uh1);
                *(uint2*)&Al[arow][ahalf * 16 + j * 4] = make_uint2(ul0, ul1);
            }
            *(uint4*)&Bh[arow][ahalf * 16 + 0] = rbh[0];
            *(uint4*)&Bh[arow][ahalf * 16 + 8] = rbh[1];
            *(uint4*)&Bl[arow][ahalf * 16 + 0] = rbl[0];
            *(uint4*)&Bl[arow][ahalf * 16 + 8] = rbl[1];
            __syncthreads();

            if (kt + 32 < D_SZ) {
                #pragma unroll
                for (int j = 0; j < 4; j++) ra[j] = __ldg((const float4*)(xp + kt + 32 + j * 4));
                #pragma unroll
                for (int j = 0; j < 2; j++) {
                    rbh[j] = __ldg((const uint4*)(whp + kt + 32 + j * 8));
                    rbl[j] = __ldg((const uint4*)(wlp + kt + 32 + j * 8));
                }
            }

            #pragma unroll
            for (int ks = 0; ks < 2; ks++) {
                const uint32_t kso = (uint32_t)(ks * 16) * 2;   // byte offset of k-chunk
                uint32_t ah[2][4], al[2][4];
                #pragma unroll
                for (int mt = 0; mt < 2; mt++) {
                    const uint32_t roff = (uint32_t)((wm * 32 + mt * 16) * LDT) * 2 + kso + a_loff;
                    ldsm_x4(ah[mt], sAh + roff);
                    ldsm_x4(al[mt], sAl + roff);
                }
                #pragma unroll
                for (int nfp = 0; nfp < 4; nfp++) {             // n-octet pairs
                    const uint32_t boff = (uint32_t)((wn * 64 + nfp * 16) * LDT) * 2 + kso + b_loff;
                    uint32_t rh[4], rl[4];
                    ldsm_x4(rh, sBh + boff);
                    ldsm_x4(rl, sBl + boff);
                    #pragma unroll
                    for (int hh = 0; hh < 2; hh++) {
                        const int nf = nfp * 2 + hh;
                        #pragma unroll
                        for (int mt = 0; mt < 2; mt++) {
                            mma16816(acc[mt][nf], ah[mt], rh[2*hh], rh[2*hh+1]);
                            mma16816(acc[mt][nf], ah[mt], rl[2*hh], rl[2*hh+1]);
                            mma16816(acc[mt][nf], al[mt], rh[2*hh], rh[2*hh+1]);
                        }
                    }
                }
            }
        }

        // ---- epilogue with fused prep ----
        const bool isK    = (bn == 0 && wn == 0);
        const bool isBeta = (bn == 1 && wn == 1);

        #pragma unroll
        for (int mt = 0; mt < 2; mt++) {
            if (isK) {
                float ss1 = 0.0f, ss2 = 0.0f;
                #pragma unroll
                for (int nf = 0; nf < 8; nf++) {
                    ss1 = fmaf(acc[mt][nf][0], acc[mt][nf][0], fmaf(acc[mt][nf][1], acc[mt][nf][1], ss1));
                    ss2 = fmaf(acc[mt][nf][2], acc[mt][nf][2], fmaf(acc[mt][nf][3], acc[mt][nf][3], ss2));
                }
                ss1 += __shfl_xor_sync(0xffffffffu, ss1, 1);
                ss1 += __shfl_xor_sync(0xffffffffu, ss1, 2);
                ss2 += __shfl_xor_sync(0xffffffffu, ss2, 1);
                ss2 += __shfl_xor_sync(0xffffffffu, ss2, 2);
                float i1 = 1.0f / (sqrtf(ss1) + 1e-6f);
                float i2 = 1.0f / (sqrtf(ss2) + 1e-6f);
                #pragma unroll
                for (int nf = 0; nf < 8; nf++) {
                    acc[mt][nf][0] *= i1; acc[mt][nf][1] *= i1;
                    acc[mt][nf][2] *= i2; acc[mt][nf][3] *= i2;
                }
            } else if (isBeta) {
                #pragma unroll
                for (int nf = 0; nf < 8; nf++) {
                    float b0 = __ldg(&bb[nf * 8 + t4 * 2]);
                    float b1 = __ldg(&bb[nf * 8 + t4 * 2 + 1]);
                    acc[mt][nf][0] = 1.0f / (1.0f + expf(-(acc[mt][nf][0] + b0)));
                    acc[mt][nf][1] = 1.0f / (1.0f + expf(-(acc[mt][nf][1] + b1)));
                    acc[mt][nf][2] = 1.0f / (1.0f + expf(-(acc[mt][nf][2] + b0)));
                    acc[mt][nf][3] = 1.0f / (1.0f + expf(-(acc[mt][nf][3] + b1)));
                }
            }
            const int r1 = row0 + wm * 32 + mt * 16 + g8;
            #pragma unroll
            for (int nf = 0; nf < 8; nf++) {
                const int col = bn * 128 + wn * 64 + nf * 8 + t4 * 2;
                *(float2*)&g_proj[(size_t)r1 * 256 + col]       = make_float2(acc[mt][nf][0], acc[mt][nf][1]);
                *(float2*)&g_proj[(size_t)(r1 + 8) * 256 + col] = make_float2(acc[mt][nf][2], acc[mt][nf][3]);
            }
        }

        __syncthreads();
        if (tid == 0) {
            __threadfence();
            atomicAdd(&g_flag[bm], 1);   // tile ready when == 2
        }
    }
}

// trailing elementwise: r -> r*r*sigmoid(r)
__global__ __launch_bounds__(256)
void silu_kernel(float* __restrict__ out)
{
    int idx = blockIdx.x * 256 + threadIdx.x;
    float4 r = *(float4*)&out[idx * 4];
    r.x = r.x * r.x * __fdividef(1.0f, 1.0f + __expf(-r.x));
    r.y = r.y * r.y * __fdividef(1.0f, 1.0f + __expf(-r.y));
    r.z = r.z * r.z * __fdividef(1.0f, 1.0f + __expf(-r.z));
    r.w = r.w * r.w * __fdividef(1.0f, 1.0f + __expf(-r.w));
    *(float4*)&out[idx * 4] = r;
}

// ---------------- host launcher ----------------
extern "C" void kernel_launch(void* const* d_in, const int* in_sizes, int n_in,
                              void* d_out, int out_size)
{
    const float* x  = (const float*)d_in[0];
    const float* S0 = (const float*)d_in[1];
    const float* Wk = (const float*)d_in[2];
    const float* Wv = (const float*)d_in[3];
    const float* Wq = (const float*)d_in[4];
    const float* Wb = (const float*)d_in[5];
    const float* bb = (const float*)d_in[6];

    reset_kernel<<<1, N_TILES>>>();
    wconv_kernel<<<1024, 256>>>(Wk, Wv, Wq, Wb);
    fused_kernel<<<SCAN_BLOCKS + GEMM_BLOCKS, 256>>>(
        x, S0, bb, (float*)d_out, (long long)out_size);
    if ((long long)out_size >= (long long)T_MAX * 1024)
        silu_kernel<<<(T_MAX * 1024) / (256 * 4), 256>>>((float*)d_out);
}